// round 4
// baseline (speedup 1.0000x reference)
#include <cuda_runtime.h>
#include <cstdint>
#include <cstddef>

// EMA along T for x[B=8, T=8192, C=512] fp32, out[t] = 0.99*out[t-1] + 0.01*x[t], out[0]=x[0].
// Decoupled lookback with decay truncation:
//   grid = B x 16 channel-slices x 16 T-chunks (k fastest in blockIdx).
//   Each block: warp-owned cp.async loads of a 512x32 tile -> per-warp local
//   zero-start scan (z-units, z=100*s) -> publish chunk end-state E / per-lane
//   acquire-wait on E_{k-1}, E_{k-2} -> fused fixup+store:
//   out = 0.01*local + 0.01*S*0.99^(r+1),  S_carry = E_{k-1} + 0.99^512*E_{k-2}.
// Truncation error 0.99^1024 ~ 3.4e-5 << 1e-3. DRAM traffic = 268 MB (the floor).

constexpr int B_ = 8, T_ = 8192, C_ = 512;
constexpr int L_ = 512;                 // timesteps per chunk
constexpr int K_ = T_ / L_;             // 16 chunks
constexpr int CS = 32;                  // channels per block
constexpr int NS = C_ / CS;             // 16 slices
constexpr int THREADS = 128;            // 4 warps
constexpr int WSTEPS = L_ / 4;          // 128 timesteps per warp
constexpr int NBLK = B_ * NS * K_;      // 2048
constexpr int TILE_B = L_ * CS * 4;     // 65536 bytes

// 0.99^n constants (n = 128, 256, 384, 512)
#define D128 0.27625170f
#define D256 0.07631500f
#define D384 0.02108240f
#define D512 0.00582420f

__device__ float g_E[NBLK][CS];
__device__ int   g_flag[NBLK];

__device__ __forceinline__ uint32_t smem_u32(const void* p) {
    uint32_t a;
    asm("{ .reg .u64 t; cvta.to.shared.u64 t, %1; cvt.u32.u64 %0, t; }"
        : "=r"(a) : "l"(p));
    return a;
}
__device__ __forceinline__ void cp_async16(uint32_t sdst, const void* gsrc) {
    asm volatile("cp.async.cg.shared.global [%0], [%1], 16;"
                 :: "r"(sdst), "l"(gsrc) : "memory");
}
__device__ __forceinline__ void cp_commit() {
    asm volatile("cp.async.commit_group;" ::: "memory");
}
template <int N> __device__ __forceinline__ void cp_wait() {
    asm volatile("cp.async.wait_group %0;" :: "n"(N) : "memory");
}
__device__ __forceinline__ int ld_acq(const int* p) {
    int v;
    asm volatile("ld.global.acquire.gpu.b32 %0, [%1];" : "=r"(v) : "l"(p) : "memory");
    return v;
}
__device__ __forceinline__ void st_rel(int* p, int v) {
    asm volatile("st.global.release.gpu.b32 [%0], %1;" :: "l"(p), "r"(v) : "memory");
}

__global__ void zero_flags_kernel() {
    int i = blockIdx.x * blockDim.x + threadIdx.x;
    if (i < NBLK) g_flag[i] = 0;
}

__global__ void __launch_bounds__(THREADS)
ema_lookback_kernel(const float* __restrict__ x, float* __restrict__ out)
{
    extern __shared__ __align__(128) unsigned char smem_raw[];
    __shared__ float s_ends[4][CS];
    __shared__ float s_carry[CS];

    const int bid   = blockIdx.x;
    const int k     = bid & (K_ - 1);
    const int slice = (bid >> 4) & (NS - 1);
    const int b     = bid >> 8;
    const int tid   = threadIdx.x;
    const int wid   = tid >> 5;
    const int lane  = tid & 31;

    const uint32_t sbuf = smem_u32(smem_raw);

    // Slice base pointers (channel offset applied; rows stride C_ floats).
    const float* xin = x   + (size_t)b * T_ * C_ + slice * CS;
    float*       dst = out + (size_t)b * T_ * C_ + slice * CS;
    const int t0 = k * L_;

    // ---- Phase 1: each warp loads ONLY its own region (rows [wid*128, wid*128+128)).
    // Region = 128 rows x 128 B = 1024 x 16B chunks; 32 per lane. Copies a warp
    // consumes are issued exclusively by that warp's lanes, so cp_wait<0> +
    // __syncwarp gives complete + ordered visibility (no cross-warp race).
    {
        const int rbase = wid * WSTEPS;                 // first row of this region
        #pragma unroll
        for (int j = 0; j < 32; j++) {
            const int q   = j * 32 + lane;              // 0..1023
            const int row = q >> 3;
            const int seg = q & 7;
            cp_async16(sbuf + (uint32_t)(rbase + row) * 128u + (uint32_t)seg * 16u,
                       xin + (size_t)(t0 + rbase + row) * C_ + seg * 4);
        }
        cp_commit();
        cp_wait<0>();
        __syncwarp();
    }

    // ---- Phase 2: local zero-start scan (z-units), in place ----
    float z = 0.0f;
    {
        const uint32_t p0 = sbuf + (uint32_t)(wid * WSTEPS) * 128u + (uint32_t)lane * 4u;
        if (k == 0 && wid == 0) {
            // global t=0 has weight 1.0: z0 = 100*x0
            #pragma unroll 8
            for (int r = 0; r < WSTEPS; r++) {
                float xv;
                asm volatile("ld.shared.f32 %0, [%1];" : "=f"(xv) : "r"(p0 + r * 128u));
                z = fmaf(z, 0.99f, xv);
                if (r == 0) z *= 100.0f;
                asm volatile("st.shared.f32 [%0], %1;" :: "r"(p0 + r * 128u), "f"(z));
            }
        } else {
            #pragma unroll 8
            for (int r = 0; r < WSTEPS; r++) {
                float xv;
                asm volatile("ld.shared.f32 %0, [%1];" : "=f"(xv) : "r"(p0 + r * 128u));
                z = fmaf(z, 0.99f, xv);
                asm volatile("st.shared.f32 [%0], %1;" :: "r"(p0 + r * 128u), "f"(z));
            }
        }
    }
    s_ends[wid][lane] = z;
    __syncthreads();

    // ---- Phase 3a: publish block end-state (warp 3) ----
    if (wid == 3 && k < K_ - 1) {
        float E = s_ends[3][lane]
                + fmaf(D128, s_ends[2][lane],
                  fmaf(D256, s_ends[1][lane], D384 * s_ends[0][lane]));
        g_E[bid][lane] = E;
        __threadfence();
        __syncwarp();
        if (lane == 0) st_rel(&g_flag[bid], 1);
    }

    // ---- Phase 3b: wait for predecessors (per-lane acquire), compute carry (warp 0) ----
    if (wid == 0) {
        if (k > 0) {
            while (ld_acq(&g_flag[bid - 1]) == 0) __nanosleep(40);   // every lane acquires
            float E1 = __ldcg(&g_E[bid - 1][lane]);
            float E2 = 0.0f;
            if (k > 1) {
                while (ld_acq(&g_flag[bid - 2]) == 0) __nanosleep(40);
                E2 = __ldcg(&g_E[bid - 2][lane]);
            }
            s_carry[lane] = fmaf(D512, E2, E1);
        } else {
            s_carry[lane] = 0.0f;
        }
    }
    __syncthreads();

    // ---- Phase 4: fused fixup + store ----
    // State entering warp w's subchunk:
    //   S_w = sum_{j<w} 0.99^(128*(w-1-j)) * ends[j]  +  0.99^(128*w) * carry
    float S;
    {
        const float cin = s_carry[lane];
        if      (wid == 0) S = cin;
        else if (wid == 1) S = fmaf(D128, cin, s_ends[0][lane]);
        else if (wid == 2) S = fmaf(D256, cin, fmaf(D128, s_ends[0][lane], s_ends[1][lane]));
        else               S = fmaf(D384, cin,
                               fmaf(D256, s_ends[0][lane],
                               fmaf(D128, s_ends[1][lane], s_ends[2][lane])));
    }

    {
        const uint32_t p0 = sbuf + (uint32_t)(wid * WSTEPS) * 128u + (uint32_t)lane * 4u;
        float* drow = dst + (size_t)(t0 + wid * WSTEPS) * C_ + lane;
        float m = S * 0.0099f;          // 0.01 * S * 0.99^(r+1), r=0
        #pragma unroll 8
        for (int r = 0; r < WSTEPS; r++) {
            float loc;
            asm volatile("ld.shared.f32 %0, [%1];" : "=f"(loc) : "r"(p0 + r * 128u));
            __stcs(drow + (size_t)r * C_, fmaf(loc, 0.01f, m));
            m *= 0.99f;
        }
    }
}

extern "C" void kernel_launch(void* const* d_in, const int* in_sizes, int n_in,
                              void* d_out, int out_size)
{
    const float* x = (const float*)d_in[0];
    float* out = (float*)d_out;
    (void)in_sizes; (void)n_in; (void)out_size;

    zero_flags_kernel<<<(NBLK + 1023) / 1024, 1024>>>();

    cudaFuncSetAttribute(ema_lookback_kernel,
                         cudaFuncAttributeMaxDynamicSharedMemorySize, TILE_B);
    ema_lookback_kernel<<<NBLK, THREADS, TILE_B>>>(x, out);
}